// round 16
// baseline (speedup 1.0000x reference)
#include <cuda_runtime.h>
#include <cstdint>

#define HF 256
#define GFG 256
#define LATF 64
#define NMAX 50000
#define EMAX 300000
#define BN_EPS 1e-5f

__device__ __align__(128) float g_X[NMAX * HF];
__device__ __align__(128) float g_Y[NMAX * HF];
__device__ __align__(128) float g_HGW[GFG * HF];
__device__ __align__(16) float g_S5[5][HF];   // zeroed by k_hist block 0
__device__ __align__(16) float g_SS5[5][HF];
__device__ int g_deg[NMAX];                   // zero at entry (k_scan re-zeroes)
__device__ int g_rowptr[NMAX + 1];
__device__ int g_cursor[NMAX];
__device__ __align__(16) int2 g_epack[EMAX];

typedef unsigned long long u64;

__device__ __forceinline__ u64 pk2(float lo, float hi) {
    u64 r; asm("mov.b64 %0,{%1,%2};" : "=l"(r) : "f"(lo), "f"(hi)); return r;
}
__device__ __forceinline__ void upk2(u64 v, float& lo, float& hi) {
    asm("mov.b64 {%0,%1},%2;" : "=f"(lo), "=f"(hi) : "l"(v));
}
__device__ __forceinline__ u64 addx2(u64 a, u64 b) {
    u64 r; asm("add.rn.f32x2 %0,%1,%2;" : "=l"(r) : "l"(a), "l"(b)); return r;
}
__device__ __forceinline__ u64 mulx2(u64 a, u64 b) {
    u64 r; asm("mul.rn.f32x2 %0,%1,%2;" : "=l"(r) : "l"(a), "l"(b)); return r;
}
__device__ __forceinline__ u64 fmax2(u64 a, u64 b, u64 c) {
    u64 r; asm("fma.rn.f32x2 %0,%1,%2,%3;" : "=l"(r) : "l"(a), "l"(b), "l"(c)); return r;
}
__device__ __forceinline__ float ex2f(float x) {
    float r; asm("ex2.approx.ftz.f32 %0,%1;" : "=f"(r) : "f"(x)); return r;
}
__device__ __forceinline__ float lg2f(float x) {
    float r; asm("lg2.approx.ftz.f32 %0,%1;" : "=f"(r) : "f"(x)); return r;
}

#define ABS2  0x7FFFFFFF7FFFFFFFULL
#define NL2E2 0xBFB8AA3BBFB8AA3BULL
#define PA1 0.99949556f
#define PA2 -0.49190896f
#define PA3 0.28947478f
#define PA4 -0.13606275f
#define PA5 0.03215845f
__device__ __forceinline__ u64 cx2(float v) { return pk2(v, v); }

__device__ __forceinline__ void sp2_acc(u64& acc, u64 x, u64 w) {
    u64 v  = addx2(x, w);
    u64 nz = mulx2(v & ABS2, NL2E2);
    float n0, n1; upk2(nz, n0, n1);
    u64 t = pk2(ex2f(n0), ex2f(n1));
    u64 p = fmax2(t, cx2(PA5), cx2(PA4));
    p = fmax2(t, p, cx2(PA3));
    p = fmax2(t, p, cx2(PA2));
    p = fmax2(t, p, cx2(PA1));
    float v0, v1; upk2(v, v0, v1);
    u64 m = pk2(fmaxf(v0, 0.f), fmaxf(v1, 0.f));
    acc = fmax2(t, p, acc);
    acc = addx2(acc, m);
}

__device__ __forceinline__ float sp(float x) {
    float t = ex2f(-fabsf(x) * 1.4426950408889634f);
    return fmaxf(x, 0.f) + lg2f(1.f + t) * 0.6931471805599453f;
}

__device__ __forceinline__ int lb(const int* __restrict__ a, int n, int key) {
    int lo = 0, hi = n;
    while (lo < hi) { int mid = (lo + hi) >> 1; if (a[mid] < key) lo = mid + 1; else hi = mid; }
    return lo;
}

__device__ __forceinline__ uint32_t f2tf32(float x) {
    uint32_t r; asm("cvt.rna.tf32.f32 %0, %1;" : "=r"(r) : "f"(x)); return r;
}

__device__ __forceinline__ void mma_tf32(float c[4], uint32_t a0, uint32_t a1,
                                         uint32_t a2, uint32_t a3,
                                         uint32_t b0, uint32_t b1) {
    asm volatile(
        "mma.sync.aligned.m16n8k8.row.col.f32.tf32.tf32.f32 "
        "{%0,%1,%2,%3}, {%4,%5,%6,%7}, {%8,%9}, {%0,%1,%2,%3};"
        : "+f"(c[0]), "+f"(c[1]), "+f"(c[2]), "+f"(c[3])
        : "r"(a0), "r"(a1), "r"(a2), "r"(a3), "r"(b0), "r"(b1));
}

__device__ __forceinline__ void coef_f(int slot, int f, const float* gam, const float* bet,
                                       float inv_n, float& sc, float& sh) {
    float s = g_S5[slot][f], q = g_SS5[slot][f];
    float mu  = s * inv_n;
    float var = q * inv_n - mu * mu;
    sc = __ldg(gam + f) * rsqrtf(var + BN_EPS);
    sh = __ldg(bet + f) - mu * sc;
}

// ---------------- CSR build ----------------
__global__ void k_hist(const int* __restrict__ dst, int e_cnt) {
    if (blockIdx.x == 0) {
        float* S = &g_S5[0][0];
        float* Q = &g_SS5[0][0];
        for (int i = threadIdx.x; i < 5 * HF; i += 256) { S[i] = 0.f; Q[i] = 0.f; }
    }
    int e = blockIdx.x * blockDim.x + threadIdx.x;
    if (e < e_cnt) atomicAdd(&g_deg[dst[e]], 1);
}

__global__ void k_scan(int n) {
    __shared__ int sm[1024];
    int t = threadIdx.x;
    int chunk = (n + 1023) >> 10;
    int lo = t * chunk, hi = min(lo + chunk, n);
    int sum = 0;
    int i = lo;
    for (; i + 4 <= hi; i += 4) {
        int d0 = g_deg[i], d1 = g_deg[i + 1], d2 = g_deg[i + 2], d3 = g_deg[i + 3];
        sum += d0 + d1 + d2 + d3;
    }
    for (; i < hi; i++) sum += g_deg[i];
    sm[t] = sum;
    __syncthreads();
    for (int off = 1; off < 1024; off <<= 1) {
        int v = (t >= off) ? sm[t - off] : 0;
        __syncthreads();
        sm[t] += v;
        __syncthreads();
    }
    int run = sm[t] - sum;
    i = lo;
    for (; i + 4 <= hi; i += 4) {
        int d0 = g_deg[i], d1 = g_deg[i + 1], d2 = g_deg[i + 2], d3 = g_deg[i + 3];
        g_rowptr[i] = run;     g_cursor[i] = run;     g_deg[i] = 0;     run += d0;
        g_rowptr[i + 1] = run; g_cursor[i + 1] = run; g_deg[i + 1] = 0; run += d1;
        g_rowptr[i + 2] = run; g_cursor[i + 2] = run; g_deg[i + 2] = 0; run += d2;
        g_rowptr[i + 3] = run; g_cursor[i + 3] = run; g_deg[i + 3] = 0; run += d3;
    }
    for (; i < hi; i++) {
        int d = g_deg[i];
        g_rowptr[i] = run; g_cursor[i] = run; g_deg[i] = 0;
        run += d;
    }
    if (t == 1023) g_rowptr[n] = run;
}

__global__ void k_scatter_embed(const int* __restrict__ src, const int* __restrict__ dst,
                                const int* __restrict__ et, int e_cnt, int e_blocks,
                                const int* __restrict__ nt, const float* __restrict__ emb,
                                int n) {
    if ((int)blockIdx.x < e_blocks) {
        int e = blockIdx.x * blockDim.x + threadIdx.x;
        if (e < e_cnt) {
            int pos = atomicAdd(&g_cursor[dst[e]], 1);
            g_epack[pos] = make_int2(src[e] << 6, et[e] << 6);
        }
    } else {
        int i = (blockIdx.x - e_blocks) * blockDim.x + threadIdx.x;
        int total = n * (HF / 4);
        if (i < total) {
            int node = i / (HF / 4);
            int f4   = i % (HF / 4);
            ((float4*)g_X)[i] = __ldg((const float4*)emb + (size_t)nt[node] * (HF / 4) + f4);
        }
    }
}

// ---- conv (R7 proven) ----
__global__ void __launch_bounds__(256) k_conv_csr(const float* __restrict__ ew, int n) {
    int grp = threadIdx.x >> 5, lane = threadIdx.x & 31;
    int node = blockIdx.x * 8 + grp;
    if (node >= n) return;
    int lo = g_rowptr[node], hi = g_rowptr[node + 1];
    const float4* X4 = (const float4*)g_X;
    const float4* W4 = (const float4*)ew;
    int c = lane << 1;
    size_t nb = (size_t)node * 64 + c;
    float4 i0 = X4[nb], i1 = X4[nb + 1];
    u64 a0 = pk2(i0.x, i0.y), a1 = pk2(i0.z, i0.w);
    u64 a2 = pk2(i1.x, i1.y), a3 = pk2(i1.z, i1.w);
    if (lo < hi) {
        int2 se = __ldg(&g_epack[lo]);
        const float4* xs = X4 + (size_t)(se.x + c);
        const float4* ws = W4 + (size_t)(se.y + c);
        float4 x0 = xs[0], x1 = xs[1];
        float4 w0 = __ldg(ws), w1 = __ldg(ws + 1);
        for (int k = lo + 1; k < hi; k++) {
            int2 se2 = __ldg(&g_epack[k]);
            const float4* xs2 = X4 + (size_t)(se2.x + c);
            const float4* ws2 = W4 + (size_t)(se2.y + c);
            float4 nx0 = xs2[0], nx1 = xs2[1];
            float4 nw0 = __ldg(ws2), nw1 = __ldg(ws2 + 1);
            sp2_acc(a0, pk2(x0.x, x0.y), pk2(w0.x, w0.y));
            sp2_acc(a1, pk2(x0.z, x0.w), pk2(w0.z, w0.w));
            sp2_acc(a2, pk2(x1.x, x1.y), pk2(w1.x, w1.y));
            sp2_acc(a3, pk2(x1.z, x1.w), pk2(w1.z, w1.w));
            x0 = nx0; x1 = nx1; w0 = nw0; w1 = nw1;
        }
        sp2_acc(a0, pk2(x0.x, x0.y), pk2(w0.x, w0.y));
        sp2_acc(a1, pk2(x0.z, x0.w), pk2(w0.z, w0.w));
        sp2_acc(a2, pk2(x1.x, x1.y), pk2(w1.x, w1.y));
        sp2_acc(a3, pk2(x1.z, x1.w), pk2(w1.z, w1.w));
    }
    float4 o0, o1;
    upk2(a0, o0.x, o0.y); upk2(a1, o0.z, o0.w);
    upk2(a2, o1.x, o1.y); upk2(a3, o1.z, o1.w);
    ((float4*)g_Y)[nb] = o0;
    ((float4*)g_Y)[nb + 1] = o1;
}

// per-feature sum/sumsq of g_Y into slot; MLP-8
__global__ void __launch_bounds__(256) k_stats(int slot, int n, int h) {
    int h4  = h >> 2;
    int gpb = 256 / h4;
    int col = threadIdx.x & (h4 - 1);
    int rof = threadIdx.x / h4;
    int stride = gridDim.x * gpb;
    float4 s  = make_float4(0.f, 0.f, 0.f, 0.f);
    float4 ss = make_float4(0.f, 0.f, 0.f, 0.f);
    const float4* Y4 = (const float4*)g_Y;
    for (int base = blockIdx.x * gpb + rof; base < n; base += stride * 8) {
        float4 v[8];
#pragma unroll
        for (int j = 0; j < 8; j++) {
            int r = base + j * stride;
            v[j] = (r < n) ? Y4[(size_t)r * h4 + col] : make_float4(0.f, 0.f, 0.f, 0.f);
        }
#pragma unroll
        for (int j = 0; j < 8; j++) {
            s.x += v[j].x; s.y += v[j].y; s.z += v[j].z; s.w += v[j].w;
            ss.x = fmaf(v[j].x, v[j].x, ss.x);
            ss.y = fmaf(v[j].y, v[j].y, ss.y);
            ss.z = fmaf(v[j].z, v[j].z, ss.z);
            ss.w = fmaf(v[j].w, v[j].w, ss.w);
        }
    }
    __shared__ float4 sh_s[256], sh_q[256];
    sh_s[threadIdx.x] = s;
    sh_q[threadIdx.x] = ss;
    __syncthreads();
    if (rof == 0) {
        for (int j = 1; j < gpb; j++) {
            float4 o = sh_s[j * h4 + col], q = sh_q[j * h4 + col];
            s.x += o.x; s.y += o.y; s.z += o.z; s.w += o.w;
            ss.x += q.x; ss.y += q.y; ss.z += q.z; ss.w += q.w;
        }
        int f = col << 2;
        float* S = &g_S5[slot][0];
        float* Q = &g_SS5[slot][0];
        atomicAdd(&S[f + 0], s.x);  atomicAdd(&S[f + 1], s.y);
        atomicAdd(&S[f + 2], s.z);  atomicAdd(&S[f + 3], s.w);
        atomicAdd(&Q[f + 0], ss.x); atomicAdd(&Q[f + 1], ss.y);
        atomicAdd(&Q[f + 2], ss.z); atomicAdd(&Q[f + 3], ss.w);
    }
}

// X = act(bn(Y)); inline coefs; MLP-8
template <bool ACT>
__global__ void __launch_bounds__(256) k_apply(int slot, const float* __restrict__ gam,
                                               const float* __restrict__ bet,
                                               float inv_n, int n, int h) {
    __shared__ __align__(16) float s_sc[HF], s_sh[HF];
    if (threadIdx.x < h)
        coef_f(slot, threadIdx.x, gam, bet, inv_n, s_sc[threadIdx.x], s_sh[threadIdx.x]);
    __syncthreads();

    int h4 = h >> 2;
    int total = n * h4;
    int base = blockIdx.x * 2048 + threadIdx.x;
    const float4* Y4 = (const float4*)g_Y;
    float4 y[8];
    int idx[8];
#pragma unroll
    for (int j = 0; j < 8; j++) {
        idx[j] = base + j * 256;
        y[j] = (idx[j] < total) ? Y4[idx[j]] : make_float4(0.f, 0.f, 0.f, 0.f);
    }
#pragma unroll
    for (int j = 0; j < 8; j++) {
        if (idx[j] >= total) continue;
        int f4 = idx[j] & (h4 - 1);
        float4 sc = ((const float4*)s_sc)[f4];
        float4 sh = ((const float4*)s_sh)[f4];
        float4 o;
        o.x = fmaf(y[j].x, sc.x, sh.x);
        o.y = fmaf(y[j].y, sc.y, sh.y);
        o.z = fmaf(y[j].z, sc.z, sh.z);
        o.w = fmaf(y[j].w, sc.w, sh.w);
        if (ACT) { o.x = sp(o.x); o.y = sp(o.y); o.z = sp(o.z); o.w = sp(o.w); }
        ((float4*)g_X)[idx[j]] = o;
    }
}

// fused pool + HGW; inline slot-2 coefs
__global__ void k_pool_hgw(const int* __restrict__ batch, int n,
                           const float* __restrict__ gam, const float* __restrict__ bet,
                           float inv_n,
                           const float* __restrict__ W1, const float* __restrict__ B1) {
    int g = blockIdx.x, f = threadIdx.x;
    __shared__ int slo, shi;
    __shared__ float hg[HF];
    float csc, csh;
    coef_f(2, f, gam, bet, inv_n, csc, csh);
    if (f == 0) { slo = lb(batch, n, g); shi = lb(batch, n, g + 1); }
    __syncthreads();
    float s = 0.f;
    int r = slo;
    for (; r + 4 <= shi; r += 4) {
        float v0 = g_Y[(size_t)(r + 0) * HF + f];
        float v1 = g_Y[(size_t)(r + 1) * HF + f];
        float v2 = g_Y[(size_t)(r + 2) * HF + f];
        float v3 = g_Y[(size_t)(r + 3) * HF + f];
        s += (v0 + v1) + (v2 + v3);
    }
    for (; r < shi; r++) s += g_Y[(size_t)r * HF + f];
    hg[f] = csc * s + (float)(shi - slo) * csh;
    __syncthreads();
    float acc = __ldg(B1 + f);
#pragma unroll 8
    for (int k = 0; k < HF; k++)
        acc = fmaf(hg[k], __ldg(W1 + (size_t)(HF + k) * HF + f), acc);
    g_HGW[g * HF + f] = acc;
}

// ======== TF32 TC GEMM: fragment-permuted smem [frag][lane][reg] ========
// A frags: [wm(4)*kk(4)*mt(2)][lane(32)][reg(4)] = 4096 u32/buffer
// B frags: [wn(2)*kk(4)*nt(4)][lane(32)][reg(2)] = 2048 u32/buffer
#define ASZ 4096
#define BSZ 2048
#define GEMM_SMEM ((2 * ASZ + 2 * BSZ) * 4)

template <int MODE, int AFF, bool STATS>
__global__ void __launch_bounds__(256)
k_gemm_tc(const float* __restrict__ A, const float* __restrict__ W,
          float* __restrict__ C, const float* __restrict__ bias,
          const int* __restrict__ batch, int M, int K, int Nc,
          int slotIn, int slotOut,
          const float* __restrict__ gam, const float* __restrict__ bet, float inv_n) {
    extern __shared__ uint32_t dynsm[];
    uint32_t* As = dynsm;
    uint32_t* Bs = dynsm + 2 * ASZ;
    __shared__ float smS[64], smQ[64];
    __shared__ __align__(16) float s_sc[HF], s_sh[HF];

    int tid = threadIdx.x;
    int lane = tid & 31, warp = tid >> 5;
    int wm = warp & 3, wn = warp >> 2;
    int g = lane >> 2, t = lane & 3;
    int m0 = blockIdx.y * 128, n0 = blockIdx.x * 64;

    if (AFF >= 1 && tid < K)
        coef_f(slotIn, tid, gam, bet, inv_n, s_sc[tid], s_sh[tid]);
    if (STATS && tid < 64) { smS[tid] = 0.f; smQ[tid] = 0.f; }
    if (AFF >= 1) __syncthreads();

    float acc[2][4][4];
#pragma unroll
    for (int i = 0; i < 2; i++)
#pragma unroll
        for (int j = 0; j < 4; j++)
#pragma unroll
            for (int k = 0; k < 4; k++) acc[i][j][k] = 0.f;

    // global-load coords: A 128x8 float4s (4/thread), B 32x16 float4s (2/thread)
    int a_row[4], a_c4[4];
#pragma unroll
    for (int j = 0; j < 4; j++) {
        int idx = tid + j * 256;
        a_row[j] = idx >> 3;
        a_c4[j]  = idx & 7;
    }
    int b_row[2], b_c4[2];
#pragma unroll
    for (int j = 0; j < 2; j++) {
        int idx = tid + j * 256;
        b_row[j] = idx >> 4;
        b_c4[j]  = idx & 15;
    }
    // precomputed permuted store bases
    int a_base[4], b_base[2];
#pragma unroll
    for (int j = 0; j < 4; j++) {
        int row = a_row[j], kc4 = a_c4[j];
        int frag = ((row >> 5) * 4 + (kc4 >> 1)) * 2 + ((row >> 4) & 1);
        int reg  = ((row >> 3) & 1) | ((kc4 & 1) << 1);
        int l0   = (row & 7) << 2;
        a_base[j] = frag * 128 + l0 * 4 + reg;
    }
#pragma unroll
    for (int j = 0; j < 2; j++) {
        int k = b_row[j], c0 = b_c4[j] << 2;
        int frag = ((c0 >> 5) * 4 + (k >> 3)) * 4 + ((c0 >> 3) & 3);
        int reg  = (k >> 2) & 1;
        int l0   = ((c0 & 7) << 2) + (k & 3);
        b_base[j] = frag * 64 + l0 * 2 + reg;
    }

    auto loadA = [&](int r, int kc) -> float4 {
        float4 v = *(const float4*)(A + (size_t)r * K + kc);
        if (AFF >= 1) {
            float4 sc = *(const float4*)(s_sc + kc);
            float4 sh = *(const float4*)(s_sh + kc);
            v.x = fmaf(v.x, sc.x, sh.x);
            v.y = fmaf(v.y, sc.y, sh.y);
            v.z = fmaf(v.z, sc.z, sh.z);
            v.w = fmaf(v.w, sc.w, sh.w);
            if (AFF == 2) { v.x = sp(v.x); v.y = sp(v.y); v.z = sp(v.z); v.w = sp(v.w); }
        }
        return v;
    };
    auto storeA = [&](uint32_t* buf, int j, float4 v) {
        int b = a_base[j];
        buf[b]      = f2tf32(v.x);
        buf[b + 4]  = f2tf32(v.y);
        buf[b + 8]  = f2tf32(v.z);
        buf[b + 12] = f2tf32(v.w);
    };
    auto storeB = [&](uint32_t* buf, int j, float4 v) {
        int b = b_base[j];
        buf[b]      = f2tf32(v.x);
        buf[b + 8]  = f2tf32(v.y);
        buf[b + 16] = f2tf32(v.z);
        buf[b + 24] = f2tf32(v.w);
    };

    float4 pa[4], pb[2];
#pragma unroll
    for (int j = 0; j < 4; j++) {
        int r = m0 + a_row[j]; if (r >= M) r = M - 1;
        pa[j] = loadA(r, a_c4[j] << 2);
    }
#pragma unroll
    for (int j = 0; j < 2; j++)
        pb[j] = __ldg((const float4*)(W + (size_t)b_row[j] * Nc + n0 + (b_c4[j] << 2)));

#pragma unroll
    for (int j = 0; j < 4; j++) storeA(As, j, pa[j]);
#pragma unroll
    for (int j = 0; j < 2; j++) storeB(Bs, j, pb[j]);
    __syncthreads();

    int ktiles = K >> 5;
    int buf = 0;
    for (int kt = 0; kt < ktiles; kt++) {
        bool hn = (kt + 1 < ktiles);
        if (hn) {
            int ko = (kt + 1) << 5;
#pragma unroll
            for (int j = 0; j < 4; j++) {
                int r = m0 + a_row[j]; if (r >= M) r = M - 1;
                pa[j] = loadA(r, ko + (a_c4[j] << 2));
            }
#pragma unroll
            for (int j = 0; j < 2; j++)
                pb[j] = __ldg((const float4*)(W + (size_t)(ko + b_row[j]) * Nc + n0 + (b_c4[j] << 2)));
        }

        const uint32_t* Ab = As + buf * ASZ;
        const uint32_t* Bb = Bs + buf * BSZ;
#pragma unroll
        for (int kk = 0; kk < 4; kk++) {
            uint4 af[2];
#pragma unroll
            for (int mt = 0; mt < 2; mt++)
                af[mt] = *(const uint4*)&Ab[(((wm * 4 + kk) * 2 + mt) * 32 + lane) * 4];
            uint2 bf[4];
#pragma unroll
            for (int nt = 0; nt < 4; nt++)
                bf[nt] = *(const uint2*)&Bb[(((wn * 4 + kk) * 4 + nt) * 32 + lane) * 2];
#pragma unroll
            for (int mt = 0; mt < 2; mt++)
#pragma unroll
                for (int nt = 0; nt < 4; nt++)
                    mma_tf32(acc[mt][nt], af[mt].x, af[mt].y, af[mt].z, af[mt].w,
                             bf[nt].x, bf[nt].y);
        }

        if (hn) {
            uint32_t* An = As + (buf ^ 1) * ASZ;
            uint32_t* Bn = Bs + (buf ^ 1) * BSZ;
#pragma unroll
            for (int j = 0; j < 4; j++) storeA(An, j, pa[j]);
#pragma unroll
            for (int j = 0; j < 2; j++) storeB(Bn, j, pb[j]);
            __syncthreads();
            buf ^= 1;
        }
    }

    float csum[8], csq[8];
#pragma unroll
    for (int j = 0; j < 8; j++) { csum[j] = 0.f; csq[j] = 0.f; }

    int row_w = m0 + (wm << 5), col_w = n0 + (wn << 5);
#pragma unroll
    for (int mt = 0; mt < 2; mt++) {
#pragma unroll
        for (int half = 0; half < 2; half++) {
            int row = row_w + (mt << 4) + g + (half << 3);
            if (row >= M) continue;
            int bg = 0;
            if (MODE == 0) bg = __ldg(batch + row);
#pragma unroll
            for (int nt = 0; nt < 4; nt++) {
                int col = col_w + (nt << 3) + (t << 1);
                float v0 = acc[mt][nt][half * 2 + 0];
                float v1 = acc[mt][nt][half * 2 + 1];
                if (MODE == 0) {
                    float2 hw = *(const float2*)(g_HGW + (size_t)bg * HF + col);
                    v0 += hw.x; v1 += hw.y;
                    *(float2*)(C + (size_t)row * Nc + col) = make_float2(v0, v1);
                } else {
                    float2 b2 = *(const float2*)(bias + col);
                    v0 += b2.x; v1 += b2.y;
                    if (MODE == 1) {
                        *(float2*)(C + (size_t)row * Nc + col) = make_float2(v0, v1);
                    } else {
                        if (col < LATF)
                            *(float2*)(C + (size_t)row * LATF + col) = make_float2(v0, v1);
                        else
                            *(float2*)(C + (size_t)M * LATF + (size_t)row * LATF + (col - LATF))
                                = make_float2(v0, v1);
                    }
                }
                if (STATS) {
                    int j = nt * 2;
                    csum[j]     += v0; csq[j]     = fmaf(v0, v0, csq[j]);
                    csum[j + 1] += v1; csq[j + 1] = fmaf(v1, v1, csq[j + 1]);
                }
            }
        }
    }

    if (STATS) {
#pragma unroll
        for (int j = 0; j < 8; j++) {
            csum[j] += __shfl_xor_sync(0xffffffffu, csum[j], 4);
            csum[j] += __shfl_xor_sync(0xffffffffu, csum[j], 8);
            csum[j] += __shfl_xor_sync(0xffffffffu, csum[j], 16);
            csq[j]  += __shfl_xor_sync(0xffffffffu, csq[j], 4);
            csq[j]  += __shfl_xor_sync(0xffffffffu, csq[j], 8);
            csq[j]  += __shfl_xor_sync(0xffffffffu, csq[j], 16);
        }
        if (g == 0) {
#pragma unroll
            for (int j = 0; j < 8; j++) {
                int lc = (wn << 5) + ((j >> 1) << 3) + (t << 1) + (j & 1);
                atomicAdd(&smS[lc], csum[j]);
                atomicAdd(&smQ[lc], csq[j]);
            }
        }
        __syncthreads();
        if (tid < 64) {
            atomicAdd(&g_S5[slotOut][n0 + tid], smS[tid]);
            atomicAdd(&g_SS5[slotOut][n0 + tid], smQ[tid]);
        }
    }
}

// ---------------- launch ----------------
extern "C" void kernel_launch(void* const* d_in, const int* in_sizes, int n_in,
                              void* d_out, int out_size) {
    const int*   node_type = (const int*)d_in[0];
    const int*   edge_type = (const int*)d_in[1];
    const int*   edge_index = (const int*)d_in[2];
    const int*   batch     = (const int*)d_in[3];
    const float* node_emb  = (const float*)d_in[4];
    const float* edge_emb  = (const float*)d_in[5];
    const float* g1 = (const float*)d_in[6],  *b1 = (const float*)d_in[7];
    const float* g2 = (const float*)d_in[8],  *b2 = (const float*)d_in[9];
    const float* g3 = (const float*)d_in[10], *b3 = (const float*)d_in[11];
    const float* go1 = (const float*)d_in[12], *bo1 = (const float*)d_in[13];
    const float* go2 = (const float*)d_in[14], *bo2 = (const float*)d_in[15];
    const float* W1 = (const float*)d_in[16], *B1 = (const float*)d_in[17];
    const float* W2 = (const float*)d_in[18], *B2 = (const float*)d_in[19];
    const float* W3 = (const float*)d_in[20], *B3 = (const float*)d_in[21];

    int N = in_sizes[0];
    int E = in_sizes[1];
    const int* src = edge_index;
    const int* dst = edge_index + E;

    float *pX, *pY;
    cudaGetSymbolAddress((void**)&pX, g_X);
    cudaGetSymbolAddress((void**)&pY, g_Y);

    static bool attr_set = false;
    if (!attr_set) {
        cudaFuncSetAttribute(k_gemm_tc<0, 1, true>,
                             cudaFuncAttributeMaxDynamicSharedMemorySize, GEMM_SMEM);
        cudaFuncSetAttribute(k_gemm_tc<1, 2, true>,
                             cudaFuncAttributeMaxDynamicSharedMemorySize, GEMM_SMEM);
        cudaFuncSetAttribute(k_gemm_tc<2, 2, false>,
                             cudaFuncAttributeMaxDynamicSharedMemorySize, GEMM_SMEM);
        attr_set = true;
    }

    const int TB = 256;
    float inv_n = 1.f / (float)N;
    int emb_gr = (N * (HF / 4) + TB - 1) / TB;
    int gm = (N + 127) / 128;
    int cv_gr = (N + 7) / 8;
    int e_gr = (E + TB - 1) / TB;
    int ap_gr = (N * (HF / 4) + 2047) / 2048;

    k_hist<<<e_gr, TB>>>(dst, E);
    k_scan<<<1, 1024>>>(N);
    k_scatter_embed<<<e_gr + emb_gr, TB>>>(src, dst, edge_type, E,
                                           e_gr, node_type, node_emb, N);

    // layer 1
    k_conv_csr<<<cv_gr, TB>>>(edge_emb, N);   // profiled slot
    k_stats<<<1024, 256>>>(0, N, HF);
    k_apply<true><<<ap_gr, TB>>>(0, g1, b1, inv_n, N, HF);

    // layer 2
    k_conv_csr<<<cv_gr, TB>>>(edge_emb, N);
    k_stats<<<1024, 256>>>(1, N, HF);
    k_apply<true><<<ap_gr, TB>>>(1, g2, b2, inv_n, N, HF);

    // layer 3
    k_conv_csr<<<cv_gr, TB>>>(edge_emb, N);
    k_stats<<<1024, 256>>>(2, N, HF);

    k_pool_hgw<<<GFG, HF>>>(batch, N, g3, b3, inv_n, W1, B1);

    // GEMM1: X = bn3(Y) @ W1_top + HGW[batch], stats -> slot 3
    k_gemm_tc<0, 1, true><<<dim3(HF / 64, gm), TB, GEMM_SMEM>>>(
        pY, W1, pX, nullptr, batch, N, HF, HF, 2, 3, g3, b3, inv_n);

    // GEMM2: Y = sp(bn4(X)) @ W2 + B2, stats -> slot 4
    k_gemm_tc<1, 2, true><<<dim3(2, gm), TB, GEMM_SMEM>>>(
        pX, W2, pY, B2, nullptr, N, HF, 128, 3, 4, go1, bo1, inv_n);

    // GEMM3: out = sp(bn5(Y)) @ W3 + B3, split (mu | logvar)
    k_gemm_tc<2, 2, false><<<dim3(2, gm), TB, GEMM_SMEM>>>(
        pY, W3, (float*)d_out, B3, nullptr, N, 128, 128, 4, 0, go2, bo2, inv_n);

    (void)n_in; (void)out_size;
}

// round 17
// speedup vs baseline: 1.2446x; 1.2446x over previous
#include <cuda_runtime.h>
#include <cstdint>

#define HF 256
#define GFG 256
#define LATF 64
#define NMAX 50000
#define EMAX 300000
#define BN_EPS 1e-5f

__device__ __align__(128) float g_X[NMAX * HF];
__device__ __align__(128) float g_Y[NMAX * HF];
__device__ __align__(128) float g_HGW[GFG * HF];
__device__ __align__(16) float g_S5[5][HF];    // slots 3,4 zeroed by k_hist; 0-2 written by k_fold
__device__ __align__(16) float g_SS5[5][HF];
__device__ __align__(16) float g_Sp[32][HF];   // conv stat partials; zero at entry (k_fold re-zeroes)
__device__ __align__(16) float g_Qp[32][HF];
__device__ int g_deg[NMAX];                    // zero at entry (k_scan re-zeroes)
__device__ int g_rowptr[NMAX + 1];
__device__ int g_cursor[NMAX];
__device__ __align__(16) int2 g_epack[EMAX];

typedef unsigned long long u64;

__device__ __forceinline__ u64 pk2(float lo, float hi) {
    u64 r; asm("mov.b64 %0,{%1,%2};" : "=l"(r) : "f"(lo), "f"(hi)); return r;
}
__device__ __forceinline__ void upk2(u64 v, float& lo, float& hi) {
    asm("mov.b64 {%0,%1},%2;" : "=f"(lo), "=f"(hi) : "l"(v));
}
__device__ __forceinline__ u64 addx2(u64 a, u64 b) {
    u64 r; asm("add.rn.f32x2 %0,%1,%2;" : "=l"(r) : "l"(a), "l"(b)); return r;
}
__device__ __forceinline__ u64 mulx2(u64 a, u64 b) {
    u64 r; asm("mul.rn.f32x2 %0,%1,%2;" : "=l"(r) : "l"(a), "l"(b)); return r;
}
__device__ __forceinline__ u64 fmax2(u64 a, u64 b, u64 c) {
    u64 r; asm("fma.rn.f32x2 %0,%1,%2,%3;" : "=l"(r) : "l"(a), "l"(b), "l"(c)); return r;
}
__device__ __forceinline__ float ex2f(float x) {
    float r; asm("ex2.approx.ftz.f32 %0,%1;" : "=f"(r) : "f"(x)); return r;
}
__device__ __forceinline__ float lg2f(float x) {
    float r; asm("lg2.approx.ftz.f32 %0,%1;" : "=f"(r) : "f"(x)); return r;
}
__device__ __forceinline__ void red_add_v4(float* p, float4 v) {
    asm volatile("red.global.add.v4.f32 [%0], {%1,%2,%3,%4};"
                 :: "l"(p), "f"(v.x), "f"(v.y), "f"(v.z), "f"(v.w) : "memory");
}

#define ABS2  0x7FFFFFFF7FFFFFFFULL
#define NL2E2 0xBFB8AA3BBFB8AA3BULL
#define PA1 0.99949556f
#define PA2 -0.49190896f
#define PA3 0.28947478f
#define PA4 -0.13606275f
#define PA5 0.03215845f
__device__ __forceinline__ u64 cx2(float v) { return pk2(v, v); }

__device__ __forceinline__ void sp2_acc(u64& acc, u64 x, u64 w) {
    u64 v  = addx2(x, w);
    u64 nz = mulx2(v & ABS2, NL2E2);
    float n0, n1; upk2(nz, n0, n1);
    u64 t = pk2(ex2f(n0), ex2f(n1));
    u64 p = fmax2(t, cx2(PA5), cx2(PA4));
    p = fmax2(t, p, cx2(PA3));
    p = fmax2(t, p, cx2(PA2));
    p = fmax2(t, p, cx2(PA1));
    float v0, v1; upk2(v, v0, v1);
    u64 m = pk2(fmaxf(v0, 0.f), fmaxf(v1, 0.f));
    acc = fmax2(t, p, acc);
    acc = addx2(acc, m);
}

__device__ __forceinline__ float sp(float x) {
    float t = ex2f(-fabsf(x) * 1.4426950408889634f);
    return fmaxf(x, 0.f) + lg2f(1.f + t) * 0.6931471805599453f;
}

__device__ __forceinline__ int lb(const int* __restrict__ a, int n, int key) {
    int lo = 0, hi = n;
    while (lo < hi) { int mid = (lo + hi) >> 1; if (a[mid] < key) lo = mid + 1; else hi = mid; }
    return lo;
}

__device__ __forceinline__ uint32_t f2tf32(float x) {
    uint32_t r; asm("cvt.rna.tf32.f32 %0, %1;" : "=r"(r) : "f"(x)); return r;
}

__device__ __forceinline__ void mma_tf32(float c[4], uint32_t a0, uint32_t a1,
                                         uint32_t a2, uint32_t a3,
                                         uint32_t b0, uint32_t b1) {
    asm volatile(
        "mma.sync.aligned.m16n8k8.row.col.f32.tf32.tf32.f32 "
        "{%0,%1,%2,%3}, {%4,%5,%6,%7}, {%8,%9}, {%0,%1,%2,%3};"
        : "+f"(c[0]), "+f"(c[1]), "+f"(c[2]), "+f"(c[3])
        : "r"(a0), "r"(a1), "r"(a2), "r"(a3), "r"(b0), "r"(b1));
}

__device__ __forceinline__ void coef_f(int slot, int f, const float* gam, const float* bet,
                                       float inv_n, float& sc, float& sh) {
    float s = g_S5[slot][f], q = g_SS5[slot][f];
    float mu  = s * inv_n;
    float var = q * inv_n - mu * mu;
    sc = __ldg(gam + f) * rsqrtf(var + BN_EPS);
    sh = __ldg(bet + f) - mu * sc;
}

// ---------------- CSR build ----------------
__global__ void k_hist(const int* __restrict__ dst, int e_cnt) {
    if (blockIdx.x == 0) {
        float* S = &g_S5[0][0];
        float* Q = &g_SS5[0][0];
        for (int i = threadIdx.x; i < 5 * HF; i += 256) { S[i] = 0.f; Q[i] = 0.f; }
    }
    int e = blockIdx.x * blockDim.x + threadIdx.x;
    if (e < e_cnt) atomicAdd(&g_deg[dst[e]], 1);
}

__global__ void k_scan(int n) {
    __shared__ int sm[1024];
    int t = threadIdx.x;
    int chunk = (n + 1023) >> 10;
    int lo = t * chunk, hi = min(lo + chunk, n);
    int sum = 0;
    int i = lo;
    for (; i + 4 <= hi; i += 4) {
        int d0 = g_deg[i], d1 = g_deg[i + 1], d2 = g_deg[i + 2], d3 = g_deg[i + 3];
        sum += d0 + d1 + d2 + d3;
    }
    for (; i < hi; i++) sum += g_deg[i];
    sm[t] = sum;
    __syncthreads();
    for (int off = 1; off < 1024; off <<= 1) {
        int v = (t >= off) ? sm[t - off] : 0;
        __syncthreads();
        sm[t] += v;
        __syncthreads();
    }
    int run = sm[t] - sum;
    i = lo;
    for (; i + 4 <= hi; i += 4) {
        int d0 = g_deg[i], d1 = g_deg[i + 1], d2 = g_deg[i + 2], d3 = g_deg[i + 3];
        g_rowptr[i] = run;     g_cursor[i] = run;     g_deg[i] = 0;     run += d0;
        g_rowptr[i + 1] = run; g_cursor[i + 1] = run; g_deg[i + 1] = 0; run += d1;
        g_rowptr[i + 2] = run; g_cursor[i + 2] = run; g_deg[i + 2] = 0; run += d2;
        g_rowptr[i + 3] = run; g_cursor[i + 3] = run; g_deg[i + 3] = 0; run += d3;
    }
    for (; i < hi; i++) {
        int d = g_deg[i];
        g_rowptr[i] = run; g_cursor[i] = run; g_deg[i] = 0;
        run += d;
    }
    if (t == 1023) g_rowptr[n] = run;
}

__global__ void k_scatter_embed(const int* __restrict__ src, const int* __restrict__ dst,
                                const int* __restrict__ et, int e_cnt, int e_blocks,
                                const int* __restrict__ nt, const float* __restrict__ emb,
                                int n) {
    if ((int)blockIdx.x < e_blocks) {
        int e = blockIdx.x * blockDim.x + threadIdx.x;
        if (e < e_cnt) {
            int pos = atomicAdd(&g_cursor[dst[e]], 1);
            g_epack[pos] = make_int2(src[e] << 6, et[e] << 6);
        }
    } else {
        int i = (blockIdx.x - e_blocks) * blockDim.x + threadIdx.x;
        int total = n * (HF / 4);
        if (i < total) {
            int node = i / (HF / 4);
            int f4   = i % (HF / 4);
            ((float4*)g_X)[i] = __ldg((const float4*)emb + (size_t)nt[node] * (HF / 4) + f4);
        }
    }
}

// ---- conv: R7 shape + per-node stat reds into 32-way partials ----
__global__ void __launch_bounds__(256) k_conv_csr(const float* __restrict__ ew, int n) {
    int grp = threadIdx.x >> 5, lane = threadIdx.x & 31;
    int node = blockIdx.x * 8 + grp;
    if (node >= n) return;
    int lo = g_rowptr[node], hi = g_rowptr[node + 1];
    const float4* X4 = (const float4*)g_X;
    const float4* W4 = (const float4*)ew;
    int c = lane << 1;
    size_t nb = (size_t)node * 64 + c;
    float4 i0 = X4[nb], i1 = X4[nb + 1];
    u64 a0 = pk2(i0.x, i0.y), a1 = pk2(i0.z, i0.w);
    u64 a2 = pk2(i1.x, i1.y), a3 = pk2(i1.z, i1.w);
    if (lo < hi) {
        int2 se = __ldg(&g_epack[lo]);
        const float4* xs = X4 + (size_t)(se.x + c);
        const float4* ws = W4 + (size_t)(se.y + c);
        float4 x0 = xs[0], x1 = xs[1];
        float4 w0 = __ldg(ws), w1 = __ldg(ws + 1);
        for (int k = lo + 1; k < hi; k++) {
            int2 se2 = __ldg(&g_epack[k]);
            const float4* xs2 = X4 + (size_t)(se2.x + c);
            const float4* ws2 = W4 + (size_t)(se2.y + c);
            float4 nx0 = xs2[0], nx1 = xs2[1];
            float4 nw0 = __ldg(ws2), nw1 = __ldg(ws2 + 1);
            sp2_acc(a0, pk2(x0.x, x0.y), pk2(w0.x, w0.y));
            sp2_acc(a1, pk2(x0.z, x0.w), pk2(w0.z, w0.w));
            sp2_acc(a2, pk2(x1.x, x1.y), pk2(w1.x, w1.y));
            sp2_acc(a3, pk2(x1.z, x1.w), pk2(w1.z, w1.w));
            x0 = nx0; x1 = nx1; w0 = nw0; w1 = nw1;
        }
        sp2_acc(a0, pk2(x0.x, x0.y), pk2(w0.x, w0.y));
        sp2_acc(a1, pk2(x0.z, x0.w), pk2(w0.z, w0.w));
        sp2_acc(a2, pk2(x1.x, x1.y), pk2(w1.x, w1.y));
        sp2_acc(a3, pk2(x1.z, x1.w), pk2(w1.z, w1.w));
    }
    float4 o0, o1;
    upk2(a0, o0.x, o0.y); upk2(a1, o0.z, o0.w);
    upk2(a2, o1.x, o1.y); upk2(a3, o1.z, o1.w);
    ((float4*)g_Y)[nb] = o0;
    ((float4*)g_Y)[nb + 1] = o1;
    // fused stats: node's own values + squares into 32-way partial slot
    int part = blockIdx.x & 31;
    int f0 = c << 2;           // feature base for o0; o1 at f0+4
    float4 q0 = make_float4(o0.x * o0.x, o0.y * o0.y, o0.z * o0.z, o0.w * o0.w);
    float4 q1 = make_float4(o1.x * o1.x, o1.y * o1.y, o1.z * o1.z, o1.w * o1.w);
    red_add_v4(&g_Sp[part][f0], o0);
    red_add_v4(&g_Sp[part][f0 + 4], o1);
    red_add_v4(&g_Qp[part][f0], q0);
    red_add_v4(&g_Qp[part][f0 + 4], q1);
}

// fold 32 partials into slot; re-zero partials (1 block, 256 threads)
__global__ void k_fold(int slot) {
    int f = threadIdx.x;
    float s = 0.f, q = 0.f;
#pragma unroll 8
    for (int p = 0; p < 32; p++) {
        s += g_Sp[p][f];
        q += g_Qp[p][f];
        g_Sp[p][f] = 0.f;
        g_Qp[p][f] = 0.f;
    }
    g_S5[slot][f] = s;
    g_SS5[slot][f] = q;
}

// X = act(bn(Y)); inline coefs; MLP-8
template <bool ACT>
__global__ void __launch_bounds__(256) k_apply(int slot, const float* __restrict__ gam,
                                               const float* __restrict__ bet,
                                               float inv_n, int n, int h) {
    __shared__ __align__(16) float s_sc[HF], s_sh[HF];
    if (threadIdx.x < h)
        coef_f(slot, threadIdx.x, gam, bet, inv_n, s_sc[threadIdx.x], s_sh[threadIdx.x]);
    __syncthreads();

    int h4 = h >> 2;
    int total = n * h4;
    int base = blockIdx.x * 2048 + threadIdx.x;
    const float4* Y4 = (const float4*)g_Y;
    float4 y[8];
    int idx[8];
#pragma unroll
    for (int j = 0; j < 8; j++) {
        idx[j] = base + j * 256;
        y[j] = (idx[j] < total) ? Y4[idx[j]] : make_float4(0.f, 0.f, 0.f, 0.f);
    }
#pragma unroll
    for (int j = 0; j < 8; j++) {
        if (idx[j] >= total) continue;
        int f4 = idx[j] & (h4 - 1);
        float4 sc = ((const float4*)s_sc)[f4];
        float4 sh = ((const float4*)s_sh)[f4];
        float4 o;
        o.x = fmaf(y[j].x, sc.x, sh.x);
        o.y = fmaf(y[j].y, sc.y, sh.y);
        o.z = fmaf(y[j].z, sc.z, sh.z);
        o.w = fmaf(y[j].w, sc.w, sh.w);
        if (ACT) { o.x = sp(o.x); o.y = sp(o.y); o.z = sp(o.z); o.w = sp(o.w); }
        ((float4*)g_X)[idx[j]] = o;
    }
}

// fused pool + HGW; inline slot-2 coefs
__global__ void k_pool_hgw(const int* __restrict__ batch, int n,
                           const float* __restrict__ gam, const float* __restrict__ bet,
                           float inv_n,
                           const float* __restrict__ W1, const float* __restrict__ B1) {
    int g = blockIdx.x, f = threadIdx.x;
    __shared__ int slo, shi;
    __shared__ float hg[HF];
    float csc, csh;
    coef_f(2, f, gam, bet, inv_n, csc, csh);
    if (f == 0) { slo = lb(batch, n, g); shi = lb(batch, n, g + 1); }
    __syncthreads();
    float s = 0.f;
    int r = slo;
    for (; r + 4 <= shi; r += 4) {
        float v0 = g_Y[(size_t)(r + 0) * HF + f];
        float v1 = g_Y[(size_t)(r + 1) * HF + f];
        float v2 = g_Y[(size_t)(r + 2) * HF + f];
        float v3 = g_Y[(size_t)(r + 3) * HF + f];
        s += (v0 + v1) + (v2 + v3);
    }
    for (; r < shi; r++) s += g_Y[(size_t)r * HF + f];
    hg[f] = csc * s + (float)(shi - slo) * csh;
    __syncthreads();
    float acc = __ldg(B1 + f);
#pragma unroll 8
    for (int k = 0; k < HF; k++)
        acc = fmaf(hg[k], __ldg(W1 + (size_t)(HF + k) * HF + f), acc);
    g_HGW[g * HF + f] = acc;
}

// ======== TF32 TC GEMM (R15 layout, BPITCH=72 for conflict-free B loads) ========
#define APITCH 36
#define BPITCH 72
#define ASZ (128 * APITCH)
#define BSZ (32 * BPITCH)
#define GEMM_SMEM ((2 * ASZ + 2 * BSZ) * 4)

template <int MODE, int AFF, bool STATS>
__global__ void __launch_bounds__(256)
k_gemm_tc(const float* __restrict__ A, const float* __restrict__ W,
          float* __restrict__ C, const float* __restrict__ bias,
          const int* __restrict__ batch, int M, int K, int Nc,
          int slotIn, int slotOut,
          const float* __restrict__ gam, const float* __restrict__ bet, float inv_n) {
    extern __shared__ uint32_t dynsm[];
    uint32_t* As = dynsm;
    uint32_t* Bs = dynsm + 2 * ASZ;
    __shared__ float smS[64], smQ[64];
    __shared__ __align__(16) float s_sc[HF], s_sh[HF];

    int tid = threadIdx.x;
    int lane = tid & 31, warp = tid >> 5;
    int wm = warp & 3, wn = warp >> 2;
    int g = lane >> 2, t = lane & 3;
    int m0 = blockIdx.y * 128, n0 = blockIdx.x * 64;

    if (AFF >= 1 && tid < K)
        coef_f(slotIn, tid, gam, bet, inv_n, s_sc[tid], s_sh[tid]);
    if (STATS && tid < 64) { smS[tid] = 0.f; smQ[tid] = 0.f; }
    if (AFF >= 1) __syncthreads();

    float acc[2][4][4];
#pragma unroll
    for (int i = 0; i < 2; i++)
#pragma unroll
        for (int j = 0; j < 4; j++)
#pragma unroll
            for (int k = 0; k < 4; k++) acc[i][j][k] = 0.f;

    int a_row[4], a_c4[4];
#pragma unroll
    for (int j = 0; j < 4; j++) {
        int idx = tid + j * 256;
        a_row[j] = idx >> 3;
        a_c4[j]  = idx & 7;
    }
    int b_row[2], b_c4[2];
#pragma unroll
    for (int j = 0; j < 2; j++) {
        int idx = tid + j * 256;
        b_row[j] = idx >> 4;
        b_c4[j]  = idx & 15;
    }

    auto loadA = [&](int r, int kc) -> float4 {
        float4 v = *(const float4*)(A + (size_t)r * K + kc);
        if (AFF >= 1) {
            float4 sc = *(const float4*)(s_sc + kc);
            float4 sh = *(const float4*)(s_sh + kc);
            v.x = fmaf(v.x, sc.x, sh.x);
            v.y = fmaf(v.y, sc.y, sh.y);
            v.z = fmaf(v.z, sc.z, sh.z);
            v.w = fmaf(v.w, sc.w, sh.w);
            if (AFF == 2) { v.x = sp(v.x); v.y = sp(v.y); v.z = sp(v.z); v.w = sp(v.w); }
        }
        return v;
    };

    float4 pa[4], pb[2];
#pragma unroll
    for (int j = 0; j < 4; j++) {
        int r = m0 + a_row[j]; if (r >= M) r = M - 1;
        pa[j] = loadA(r, a_c4[j] << 2);
    }
#pragma unroll
    for (int j = 0; j < 2; j++)
        pb[j] = __ldg((const float4*)(W + (size_t)b_row[j] * Nc + n0 + (b_c4[j] << 2)));

#pragma unroll
    for (int j = 0; j < 4; j++) {
        uint4 u = make_uint4(f2tf32(pa[j].x), f2tf32(pa[j].y),
                             f2tf32(pa[j].z), f2tf32(pa[j].w));
        *(uint4*)&As[a_row[j] * APITCH + (a_c4[j] << 2)] = u;
    }
#pragma unroll
    for (int j = 0; j < 2; j++) {
        uint4 u = make_uint4(f2tf32(pb[j].x), f2tf32(pb[j].y),
                             f2tf32(pb[j].z), f2tf32(pb[j].w));
        *(uint4*)&Bs[b_row[j] * BPITCH + (b_c4[j] << 2)] = u;
    }
    __syncthreads();

    int ktiles = K >> 5;
    int buf = 0;
    for (int kt = 0; kt < ktiles; kt++) {
        bool hn = (kt + 1 < ktiles);
        if (hn) {
            int ko = (kt + 1) << 5;
#pragma unroll
            for (int j = 0; j < 4; j++) {
                int r = m0 + a_row[j]; if (r >= M) r = M - 1;
                pa[j] = loadA(r, ko + (a_c4[j] << 2));
            }
#pragma unroll
            for (int j = 0; j < 2; j++)
                pb[j] = __ldg((const float4*)(W + (size_t)(ko + b_row[j]) * Nc + n0 + (b_c4[j] << 2)));
        }

        const uint32_t* Ab = As + buf * ASZ;
        const uint32_t* Bb = Bs + buf * BSZ;
#pragma unroll
        for (int kk = 0; kk < 4; kk++) {
            int k8 = kk << 3;
            uint32_t af[2][4];
#pragma unroll
            for (int mt = 0; mt < 2; mt++) {
                int r = (wm << 5) + (mt << 4) + g;
                af[mt][0] = Ab[r * APITCH + k8 + t];
                af[mt][1] = Ab[(r + 8) * APITCH + k8 + t];
                af[mt][2] = Ab[r * APITCH + k8 + t + 4];
                af[mt][3] = Ab[(r + 8) * APITCH + k8 + t + 4];
            }
            uint32_t bf[4][2];
#pragma unroll
            for (int nt = 0; nt < 4; nt++) {
                int c = (wn << 5) + (nt << 3) + g;
                bf[nt][0] = Bb[(k8 + t) * BPITCH + c];
                bf[nt][1] = Bb[(k8 + t + 4) * BPITCH + c];
            }
#pragma unroll
            for (int mt = 0; mt < 2; mt++)
#pragma unroll
                for (int nt = 0; nt < 4; nt++)
                    mma_tf32(acc[mt][nt], af[mt][0], af[mt][1], af[mt][2], af[mt][3],
                             bf[nt][0], bf[nt][1]);
        }

        if (hn) {
            uint32_t* An = As + (buf ^ 1) * ASZ;
            uint32_t* Bn = Bs + (buf ^ 1) * BSZ;
#pragma unroll
            for (int j = 0; j < 4; j++) {
                uint4 u = make_uint4(f2tf32(pa[j].x), f2tf32(pa[j].y),
                                     f2tf32(pa[j].z), f2tf32(pa[j].w));
                *(uint4*)&An[a_row[j] * APITCH + (a_c4[j] << 2)] = u;
            }
#pragma unroll
            for (int j = 0; j < 2; j++) {
                uint4 u = make_uint4(f2tf32(pb[j].x), f2tf32(pb[j].y),
                                     f2tf32(pb[j].z), f2tf32(pb[j].w));
                *(uint4*)&Bn[b_row[j] * BPITCH + (b_c4[j] << 2)] = u;
            }
            __syncthreads();
            buf ^= 1;
        }
    }

    float csum[8], csq[8];
#pragma unroll
    for (int j = 0; j < 8; j++) { csum[j] = 0.f; csq[j] = 0.f; }

    int row_w = m0 + (wm << 5), col_w = n0 + (wn << 5);
#pragma unroll
    for (int mt = 0; mt < 2; mt++) {
#pragma unroll
        for (int half = 0; half < 2; half++) {
            int row = row_w + (mt << 4) + g + (half << 3);
            if (row >= M) continue;
            int bg = 0;
            if (MODE == 0) bg = __ldg(batch + row);
#pragma unroll
            for (int nt = 0; nt < 4; nt++) {
                int col = col_w + (nt << 3) + (t << 1);
                float v0 = acc[mt][nt][half * 2 + 0];
                float v1 = acc[mt][nt][half * 2 + 1];
                if (MODE == 0) {
                    float2 hw = *(const float2*)(g_HGW + (size_t)bg * HF + col);
                    v0 += hw.x; v1 += hw.y;
                    *(float2*)(C + (size_t)row * Nc + col) = make_float2(v0, v1);
                } else {
                    float2 b2 = *(const float2*)(bias + col);
                    v0 += b2.x; v1 += b2.y;
                    if (MODE == 1) {
                        *(float2*)(C + (size_t)row * Nc + col) = make_float2(v0, v1);
                    } else {
                        if (col < LATF)
                            *(float2*)(C + (size_t)row * LATF + col) = make_float2(v0, v1);
                        else
                            *(float2*)(C + (size_t)M * LATF + (size_t)row * LATF + (col - LATF))
                                = make_float2(v0, v1);
                    }
                }
                if (STATS) {
                    int j = nt * 2;
                    csum[j]     += v0; csq[j]     = fmaf(v0, v0, csq[j]);
                    csum[j + 1] += v1; csq[j + 1] = fmaf(v1, v1, csq[j + 1]);
                }
            }
        }
    }

    if (STATS) {
#pragma unroll
        for (int j = 0; j < 8; j++) {
            csum[j] += __shfl_xor_sync(0xffffffffu, csum[j], 4);
            csum[j] += __shfl_xor_sync(0xffffffffu, csum[j], 8);
            csum[j] += __shfl_xor_sync(0xffffffffu, csum[j], 16);
            csq[j]  += __shfl_xor_sync(0xffffffffu, csq[j], 4);
            csq[j]  += __shfl_xor_sync(0xffffffffu, csq[j], 8);
            csq[j]  += __shfl_xor_sync(0xffffffffu, csq[j], 16);
        }
        if (g == 0) {
#pragma unroll
            for (int j = 0; j < 8; j++) {
                int lc = (wn << 5) + ((j >> 1) << 3) + (t << 1) + (j & 1);
                atomicAdd(&smS[lc], csum[j]);
                atomicAdd(&smQ[lc], csq[j]);
            }
        }
        __syncthreads();
        if (tid < 64) {
            atomicAdd(&g_S5[slotOut][n0 + tid], smS[tid]);
            atomicAdd(&g_SS5[slotOut][n0 + tid], smQ[tid]);
        }
    }
}

// ---------------- launch ----------------
extern "C" void kernel_launch(void* const* d_in, const int* in_sizes, int n_in,
                              void* d_out, int out_size) {
    const int*   node_type = (const int*)d_in[0];
    const int*   edge_type = (const int*)d_in[1];
    const int*   edge_index = (const int*)d_in[2];
    const int*   batch     = (const int*)d_in[3];
    const float* node_emb  = (const float*)d_in[4];
    const float* edge_emb  = (const float*)d_in[5];
    const float* g1 = (const float*)d_in[6],  *b1 = (const float*)d_in[7];
    const float* g2 = (const float*)d_in[8],  *b2 = (const float*)d_in[9];
    const float* g3 = (const float*)d_in[10], *b3 = (const float*)d_in[11];
    const float* go1 = (const float*)d_in[12], *bo1 = (const float*)d_in[13];
    const float* go2 = (const float*)d_in[14], *bo2 = (const float*)d_in[15];
    const float* W1 = (const float*)d_in[16], *B1 = (const float*)d_in[17];
    const float* W2 = (const float*)d_in[18], *B2 = (const float*)d_in[19];
    const float* W3 = (const float*)d_in[20], *B3 = (const float*)d_in[21];

    int N = in_sizes[0];
    int E = in_sizes[1];
    const int* src = edge_index;
    const int* dst = edge_index + E;

    float *pX, *pY;
    cudaGetSymbolAddress((void**)&pX, g_X);
    cudaGetSymbolAddress((void**)&pY, g_Y);

    static bool attr_set = false;
    if (!attr_set) {
        cudaFuncSetAttribute(k_gemm_tc<0, 1, true>,
                             cudaFuncAttributeMaxDynamicSharedMemorySize, GEMM_SMEM);
        cudaFuncSetAttribute(k_gemm_tc<1, 2, true>,
                             cudaFuncAttributeMaxDynamicSharedMemorySize, GEMM_SMEM);
        cudaFuncSetAttribute(k_gemm_tc<2, 2, false>,
                             cudaFuncAttributeMaxDynamicSharedMemorySize, GEMM_SMEM);
        attr_set = true;
    }

    const int TB = 256;
    float inv_n = 1.f / (float)N;
    int emb_gr = (N * (HF / 4) + TB - 1) / TB;
    int gm = (N + 127) / 128;
    int cv_gr = (N + 7) / 8;
    int e_gr = (E + TB - 1) / TB;
    int ap_gr = (N * (HF / 4) + 2047) / 2048;

    k_hist<<<e_gr, TB>>>(dst, E);
    k_scan<<<1, 1024>>>(N);
    k_scatter_embed<<<e_gr + emb_gr, TB>>>(src, dst, edge_type, E,
                                           e_gr, node_type, node_emb, N);

    // layer 1 (conv has fused partial stats)
    k_conv_csr<<<cv_gr, TB>>>(edge_emb, N);   // profiled slot 4
    k_fold<<<1, HF>>>(0);
    k_apply<true><<<ap_gr, TB>>>(0, g1, b1, inv_n, N, HF);

    // layer 2
    k_conv_csr<<<cv_gr, TB>>>(edge_emb, N);
    k_fold<<<1, HF>>>(1);
    k_apply<true><<<ap_gr, TB>>>(1, g2, b2, inv_n, N, HF);

    // layer 3
    k_conv_csr<<<cv_gr, TB>>>(edge_emb, N);
    k_fold<<<1, HF>>>(2);

    k_pool_hgw<<<GFG, HF>>>(batch, N, g3, b3, inv_n, W1, B1);

    // GEMM1: X = bn3(Y) @ W1_top + HGW[batch], stats -> slot 3
    k_gemm_tc<0, 1, true><<<dim3(HF / 64, gm), TB, GEMM_SMEM>>>(
        pY, W1, pX, nullptr, batch, N, HF, HF, 2, 3, g3, b3, inv_n);

    // GEMM2: Y = sp(bn4(X)) @ W2 + B2, stats -> slot 4
    k_gemm_tc<1, 2, true><<<dim3(2, gm), TB, GEMM_SMEM>>>(
        pX, W2, pY, B2, nullptr, N, HF, 128, 3, 4, go1, bo1, inv_n);

    // GEMM3: out = sp(bn5(Y)) @ W3 + B3, split (mu | logvar)
    k_gemm_tc<2, 2, false><<<dim3(2, gm), TB, GEMM_SMEM>>>(
        pY, W3, (float*)d_out, B3, nullptr, N, 128, 128, 4, 0, go2, bo2, inv_n);

    (void)n_in; (void)out_size;
}